// round 1
// baseline (speedup 1.0000x reference)
#include <cuda_runtime.h>
#include <math.h>

#define Lq   3072
#define Dm   1024
#define NH   16
#define HDim 64
#define Sc   512
#define DFFm 4096
#define NBlk 2

// ---------------- scratch (device globals: allocation-guard-safe) ----------
__device__ float g_x [Lq*Dm];
__device__ float g_hx[Lq*Dm];
__device__ float g_ff[Lq*DFFm];
__device__ float g_q [Lq*Dm];
__device__ float g_k [Lq*Dm];
__device__ float g_v [Lq*Dm];
__device__ float g_o [Lq*Dm];
__device__ float g_ck[Sc*Dm];
__device__ float g_cv[Sc*Dm];
__device__ float g_mods[6*Dm];

// ---------------- trivial copy ---------------------------------------------
__global__ void copy_kernel(const float* __restrict__ src, float* __restrict__ dst, int n4){
    int i = blockIdx.x*blockDim.x + threadIdx.x;
    if(i < n4) ((float4*)dst)[i] = ((const float4*)src)[i];
}

// ---------------- modulation GEMV: mods = t @ adaW^T + adab ----------------
__global__ void mod_gemv(const float* __restrict__ t, const float* __restrict__ W,
                         const float* __restrict__ b, float* __restrict__ out){
    int o    = blockIdx.x*8 + (threadIdx.x>>5);
    int lane = threadIdx.x & 31;
    const float* w = W + (size_t)o*Dm;
    float s = 0.f;
    for(int k=lane;k<Dm;k+=32) s += t[k]*w[k];
    #pragma unroll
    for(int off=16;off;off>>=1) s += __shfl_xor_sync(0xffffffffu, s, off);
    if(lane==0) out[o] = s + b[o];
}

// ---------------- layernorm (+ optional shift/scale modulation) ------------
__global__ void ln_mod(const float* __restrict__ x, const float* __restrict__ mods,
                       int sh_off, int sc_off, float* __restrict__ out){
    int row = blockIdx.x; int t = threadIdx.x;
    const float* xr = x + (size_t)row*Dm;
    float v[4];
    #pragma unroll
    for(int i=0;i<4;i++) v[i] = xr[t + 256*i];
    __shared__ float red[256];
    float s = v[0]+v[1]+v[2]+v[3];
    red[t]=s; __syncthreads();
    #pragma unroll
    for(int o=128;o>0;o>>=1){ if(t<o) red[t]+=red[t+o]; __syncthreads(); }
    float mean = red[0]*(1.f/Dm);
    __syncthreads();
    float sq = 0.f;
    #pragma unroll
    for(int i=0;i<4;i++){ float d=v[i]-mean; sq += d*d; }
    red[t]=sq; __syncthreads();
    #pragma unroll
    for(int o=128;o>0;o>>=1){ if(t<o) red[t]+=red[t+o]; __syncthreads(); }
    float rstd = rsqrtf(red[0]*(1.f/Dm) + 1e-6f);
    float* orow = out + (size_t)row*Dm;
    #pragma unroll
    for(int i=0;i<4;i++){
        int c = t + 256*i;
        float y = (v[i]-mean)*rstd;
        if(sh_off >= 0) y = y*(1.f + mods[sc_off + c]) + mods[sh_off + c];
        orow[c] = y;
    }
}

// ---------------- 3D RoPE on q,k (head-dim angle shared across heads) ------
__global__ void rope_qk(float* __restrict__ q, float* __restrict__ k,
                        const float* __restrict__ rope){
    int id = blockIdx.x*blockDim.x + threadIdx.x;
    if(id >= Lq*NH*32) return;
    int d = id & 31;
    int h = (id>>5) & (NH-1);
    int l = id >> 9;
    float a1 = rope[l*HDim + d], a2 = rope[l*HDim + d + 32];
    float s1,c1,s2,c2;
    sincosf(a1,&s1,&c1);
    sincosf(a2,&s2,&c2);
    size_t base = (size_t)l*Dm + h*HDim;
    float q1=q[base+d], q2=q[base+d+32];
    q[base+d]    = q1*c1 - q2*s1;
    q[base+d+32] = q2*c2 + q1*s2;
    float k1=k[base+d], k2=k[base+d+32];
    k[base+d]    = k1*c1 - k2*s1;
    k[base+d+32] = k2*c2 + k1*s2;
}

// ---------------- flash attention, fp32, HD=64 ------------------------------
// grid (Lq/64, NH), 64 threads; one thread = one query row, online softmax
// in chunks of 8 keys so score regs stay register-resident.
__global__ __launch_bounds__(64) void attn_fp32(
        const float* __restrict__ Q, const float* __restrict__ K,
        const float* __restrict__ V, float* __restrict__ O, int nkv){
    __shared__ float Ks[64][HDim];
    __shared__ float Vs[64][HDim];
    int h  = blockIdx.y;
    int q0 = blockIdx.x*64;
    int t  = threadIdx.x;
    float qv[HDim], acc[HDim];
    const float* qr = Q + (size_t)(q0+t)*Dm + h*HDim;
    #pragma unroll
    for(int d=0;d<HDim;d++){ qv[d]=qr[d]*0.125f; acc[d]=0.f; }
    float m = -1e30f, lsum = 0.f;
    for(int kv0=0; kv0<nkv; kv0+=64){
        #pragma unroll
        for(int i=0;i<16;i++){
            int idx = i*64 + t;
            int r = idx>>4, c = (idx&15)<<2;
            *(float4*)&Ks[r][c] = *(const float4*)(K + (size_t)(kv0+r)*Dm + h*HDim + c);
            *(float4*)&Vs[r][c] = *(const float4*)(V + (size_t)(kv0+r)*Dm + h*HDim + c);
        }
        __syncthreads();
        #pragma unroll 1
        for(int jc=0;jc<64;jc+=8){
            float s[8]; float tmax = -1e30f;
            #pragma unroll
            for(int j=0;j<8;j++){
                const float4* kr = (const float4*)Ks[jc+j];
                float a0=0,a1=0,a2=0,a3=0;
                #pragma unroll
                for(int d4=0; d4<16; d4++){
                    float4 kk = kr[d4];
                    a0 += qv[d4*4+0]*kk.x; a1 += qv[d4*4+1]*kk.y;
                    a2 += qv[d4*4+2]*kk.z; a3 += qv[d4*4+3]*kk.w;
                }
                s[j] = (a0+a1)+(a2+a3);
                tmax = fmaxf(tmax, s[j]);
            }
            float mnew = fmaxf(m, tmax);
            float corr = __expf(m - mnew);
            lsum *= corr;
            #pragma unroll
            for(int d=0;d<HDim;d++) acc[d]*=corr;
            #pragma unroll
            for(int j=0;j<8;j++){
                float p = __expf(s[j]-mnew);
                lsum += p;
                const float4* vr = (const float4*)Vs[jc+j];
                #pragma unroll
                for(int d4=0;d4<16;d4++){
                    float4 vv = vr[d4];
                    acc[d4*4+0] += p*vv.x; acc[d4*4+1] += p*vv.y;
                    acc[d4*4+2] += p*vv.z; acc[d4*4+3] += p*vv.w;
                }
            }
            m = mnew;
        }
        __syncthreads();
    }
    float inv = 1.f/lsum;
    float* orow = O + (size_t)(q0+t)*Dm + h*HDim;
    #pragma unroll
    for(int d=0;d<HDim;d++) orow[d] = acc[d]*inv;
}

// ---------------- SGEMM NT: C[m,n] = sum_k A[m,k]*B[n,k]  -------------------
// 128x128 tile, BK=8, 256 threads, 8x8 per thread (split 2x2 of 4x4).
// gridDim.z selects among up to 3 (B,C) pairs sharing A (qkv / cross-kv fuse).
// mode: 0 = (+bias), 1 = gelu(+bias), 2 = C += (+bias), 3 = C += gate[n]*(+bias)
__global__ __launch_bounds__(256) void sgemm(
        const float* __restrict__ A,
        const float* __restrict__ B0, const float* __restrict__ B1, const float* __restrict__ B2,
        float* __restrict__ C0, float* __restrict__ C1, float* __restrict__ C2,
        const float* __restrict__ bias, const float* __restrict__ gate,
        int M, int N, int K, int mode){
    const float* B = (blockIdx.z==0) ? B0 : (blockIdx.z==1 ? B1 : B2);
    float*       C = (blockIdx.z==0) ? C0 : (blockIdx.z==1 ? C1 : C2);

    __shared__ float As[8][128];
    __shared__ float Bs[8][128];
    int tid = threadIdx.x;
    int bm = blockIdx.y*128, bn = blockIdx.x*128;
    int lr = tid>>1;            // 0..127
    int lc = (tid&1)*4;         // 0 or 4
    const float* Ag = A + (size_t)(bm+lr)*K + lc;
    const float* Bg = B + (size_t)(bn+lr)*K + lc;
    int tx = tid & 15, ty = tid >> 4;
    float acc[8][8];
    #pragma unroll
    for(int i=0;i<8;i++)
        #pragma unroll
        for(int j=0;j<8;j++) acc[i][j]=0.f;

    for(int k0=0;k0<K;k0+=8){
        float4 av = *(const float4*)(Ag + k0);
        float4 bv = *(const float4*)(Bg + k0);
        As[lc+0][lr]=av.x; As[lc+1][lr]=av.y; As[lc+2][lr]=av.z; As[lc+3][lr]=av.w;
        Bs[lc+0][lr]=bv.x; Bs[lc+1][lr]=bv.y; Bs[lc+2][lr]=bv.z; Bs[lc+3][lr]=bv.w;
        __syncthreads();
        #pragma unroll
        for(int k=0;k<8;k++){
            float a[8], b[8];
            #pragma unroll
            for(int i=0;i<4;i++){
                a[i]   = As[k][ty*4+i];
                a[4+i] = As[k][64+ty*4+i];
                b[i]   = Bs[k][tx*4+i];
                b[4+i] = Bs[k][64+tx*4+i];
            }
            #pragma unroll
            for(int i=0;i<8;i++)
                #pragma unroll
                for(int j=0;j<8;j++) acc[i][j] += a[i]*b[j];
        }
        __syncthreads();
    }

    #pragma unroll
    for(int i=0;i<8;i++){
        int m = bm + ((i<4) ? ty*4+i : 64+ty*4+(i-4));
        #pragma unroll
        for(int j=0;j<8;j++){
            int n = bn + ((j<4) ? tx*4+j : 64+tx*4+(j-4));
            float v = acc[i][j];
            if(bias) v += bias[n];
            if(mode==1)      v = 0.5f*v*(1.f + erff(v*0.70710678118f));
            else if(mode==2) v = C[(size_t)m*N+n] + v;
            else if(mode==3) v = C[(size_t)m*N+n] + gate[n]*v;
            C[(size_t)m*N+n] = v;
        }
    }
}

// ---------------- driver ----------------------------------------------------
extern "C" void kernel_launch(void* const* d_in, const int* in_sizes, int n_in,
                              void* d_out, int out_size){
    const float* x     = (const float*)d_in[0];
    const float* temb  = (const float*)d_in[1];
    const float* ctx   = (const float*)d_in[2];
    const float* rope  = (const float*)d_in[3];
    const float* adaW  = (const float*)d_in[4];
    const float* adab  = (const float*)d_in[5];
    const float* sqW   = (const float*)d_in[6];
    const float* skW   = (const float*)d_in[7];
    const float* svW   = (const float*)d_in[8];
    const float* soW   = (const float*)d_in[9];
    const float* sob   = (const float*)d_in[10];
    const float* cqW   = (const float*)d_in[11];
    const float* ckW   = (const float*)d_in[12];
    const float* cvW   = (const float*)d_in[13];
    const float* coW   = (const float*)d_in[14];
    const float* cob   = (const float*)d_in[15];
    const float* f1W   = (const float*)d_in[16];
    const float* f1b   = (const float*)d_in[17];
    const float* f2W   = (const float*)d_in[18];
    const float* f2b   = (const float*)d_in[19];

    float *px,*phx,*pff,*pq,*pk,*pv,*po,*pck,*pcv,*pmods;
    cudaGetSymbolAddress((void**)&px,   g_x);
    cudaGetSymbolAddress((void**)&phx,  g_hx);
    cudaGetSymbolAddress((void**)&pff,  g_ff);
    cudaGetSymbolAddress((void**)&pq,   g_q);
    cudaGetSymbolAddress((void**)&pk,   g_k);
    cudaGetSymbolAddress((void**)&pv,   g_v);
    cudaGetSymbolAddress((void**)&po,   g_o);
    cudaGetSymbolAddress((void**)&pck,  g_ck);
    cudaGetSymbolAddress((void**)&pcv,  g_cv);
    cudaGetSymbolAddress((void**)&pmods,g_mods);

    copy_kernel<<<(Lq*Dm/4+255)/256,256>>>(x, px, Lq*Dm/4);

    for(int i=0;i<NBlk;i++){
        const float* adaWi = adaW + (size_t)i*6*Dm*Dm;
        const float* adabi = adab + (size_t)i*6*Dm;
        const float* sqWi  = sqW  + (size_t)i*Dm*Dm;
        const float* skWi  = skW  + (size_t)i*Dm*Dm;
        const float* svWi  = svW  + (size_t)i*Dm*Dm;
        const float* soWi  = soW  + (size_t)i*Dm*Dm;
        const float* sobi  = sob  + (size_t)i*Dm;
        const float* cqWi  = cqW  + (size_t)i*Dm*Dm;
        const float* ckWi  = ckW  + (size_t)i*Dm*Dm;
        const float* cvWi  = cvW  + (size_t)i*Dm*Dm;
        const float* coWi  = coW  + (size_t)i*Dm*Dm;
        const float* cobi  = cob  + (size_t)i*Dm;
        const float* f1Wi  = f1W  + (size_t)i*DFFm*Dm;
        const float* f1bi  = f1b  + (size_t)i*DFFm;
        const float* f2Wi  = f2W  + (size_t)i*Dm*DFFm;
        const float* f2bi  = f2b  + (size_t)i*Dm;

        // adaLN modulation vector (6*D)
        mod_gemv<<<6*Dm/8,256>>>(temb, adaWi, adabi, pmods);

        // --- self attention ---
        ln_mod<<<Lq,256>>>(px, pmods, 0, Dm, phx);                       // shift_msa, scale_msa
        sgemm<<<dim3(Dm/128, Lq/128, 3),256>>>(phx, sqWi, skWi, svWi,
                                               pq, pk, pv, nullptr, nullptr,
                                               Lq, Dm, Dm, 0);
        rope_qk<<<(Lq*NH*32)/256,256>>>(pq, pk, rope);
        attn_fp32<<<dim3(Lq/64, NH),64>>>(pq, pk, pv, po, Lq);
        sgemm<<<dim3(Dm/128, Lq/128, 1),256>>>(po, soWi,nullptr,nullptr,
                                               px, nullptr,nullptr,
                                               sobi, pmods+2*Dm,        // gate_msa
                                               Lq, Dm, Dm, 3);

        // --- cross attention ---
        ln_mod<<<Lq,256>>>(px, pmods, -1, -1, phx);                      // plain LN
        sgemm<<<dim3(Dm/128, Lq/128, 1),256>>>(phx, cqWi,nullptr,nullptr,
                                               pq, nullptr,nullptr,
                                               nullptr, nullptr, Lq, Dm, Dm, 0);
        sgemm<<<dim3(Dm/128, Sc/128, 2),256>>>(ctx, ckWi, cvWi, nullptr,
                                               pck, pcv, nullptr,
                                               nullptr, nullptr, Sc, Dm, Dm, 0);
        attn_fp32<<<dim3(Lq/64, NH),64>>>(pq, pck, pcv, po, Sc);
        sgemm<<<dim3(Dm/128, Lq/128, 1),256>>>(po, coWi,nullptr,nullptr,
                                               px, nullptr,nullptr,
                                               cobi, nullptr, Lq, Dm, Dm, 2);

        // --- MLP ---
        ln_mod<<<Lq,256>>>(px, pmods, 3*Dm, 4*Dm, phx);                  // shift_mlp, scale_mlp
        sgemm<<<dim3(DFFm/128, Lq/128, 1),256>>>(phx, f1Wi,nullptr,nullptr,
                                                 pff, nullptr,nullptr,
                                                 f1bi, nullptr, Lq, DFFm, Dm, 1);
        sgemm<<<dim3(Dm/128, Lq/128, 1),256>>>(pff, f2Wi,nullptr,nullptr,
                                               px, nullptr,nullptr,
                                               f2bi, pmods+5*Dm,        // gate_mlp
                                               Lq, Dm, DFFm, 3);
    }

    copy_kernel<<<(Lq*Dm/4+255)/256,256>>>(px, (float*)d_out, Lq*Dm/4);
}

// round 2
// speedup vs baseline: 1.2587x; 1.2587x over previous
#include <cuda_runtime.h>
#include <math.h>
#include <stdint.h>

#define Lq   3072
#define Dm   1024
#define NH   16
#define HDim 64
#define Sc   512
#define DFFm 4096
#define NBlk 2

// ---------------- scratch (device globals: allocation-guard-safe) ----------
__device__ float g_x [Lq*Dm];
__device__ float g_hx[Lq*Dm];
__device__ float g_ff[Lq*DFFm];
__device__ float g_q [Lq*Dm];
__device__ float g_k [Lq*Dm];
__device__ float g_v [Lq*Dm];
__device__ float g_o [Lq*Dm];
__device__ float g_ck[Sc*Dm];
__device__ float g_cv[Sc*Dm];
__device__ float g_mods[6*Dm];

// ---------------- helpers ---------------------------------------------------
__device__ __forceinline__ uint32_t f2tf32(float f){
    uint32_t u; asm("cvt.rna.tf32.f32 %0, %1;" : "=r"(u) : "f"(f)); return u;
}
__device__ __forceinline__ void mma_tf32(float c[4], const uint32_t a[4], const uint32_t b[2]){
    asm volatile("mma.sync.aligned.m16n8k8.row.col.f32.tf32.tf32.f32 "
        "{%0,%1,%2,%3}, {%4,%5,%6,%7}, {%8,%9}, {%0,%1,%2,%3};\n"
        : "+f"(c[0]), "+f"(c[1]), "+f"(c[2]), "+f"(c[3])
        : "r"(a[0]), "r"(a[1]), "r"(a[2]), "r"(a[3]), "r"(b[0]), "r"(b[1]));
}

// ---------------- trivial copy ---------------------------------------------
__global__ void copy_kernel(const float* __restrict__ src, float* __restrict__ dst, int n4){
    int i = blockIdx.x*blockDim.x + threadIdx.x;
    if(i < n4) ((float4*)dst)[i] = ((const float4*)src)[i];
}

// ---------------- modulation GEMV: mods = t @ adaW^T + adab ----------------
__global__ void mod_gemv(const float* __restrict__ t, const float* __restrict__ W,
                         const float* __restrict__ b, float* __restrict__ out){
    int o    = blockIdx.x*8 + (threadIdx.x>>5);
    int lane = threadIdx.x & 31;
    const float* w = W + (size_t)o*Dm;
    float s = 0.f;
    for(int k=lane;k<Dm;k+=32) s += t[k]*w[k];
    #pragma unroll
    for(int off=16;off;off>>=1) s += __shfl_xor_sync(0xffffffffu, s, off);
    if(lane==0) out[o] = s + b[o];
}

// ---------------- layernorm (+ optional shift/scale modulation) ------------
__global__ void ln_mod(const float* __restrict__ x, const float* __restrict__ mods,
                       int sh_off, int sc_off, float* __restrict__ out){
    int row = blockIdx.x; int t = threadIdx.x;
    const float* xr = x + (size_t)row*Dm;
    float v[4];
    #pragma unroll
    for(int i=0;i<4;i++) v[i] = xr[t + 256*i];
    __shared__ float red[256];
    float s = v[0]+v[1]+v[2]+v[3];
    red[t]=s; __syncthreads();
    #pragma unroll
    for(int o=128;o>0;o>>=1){ if(t<o) red[t]+=red[t+o]; __syncthreads(); }
    float mean = red[0]*(1.f/Dm);
    __syncthreads();
    float sq = 0.f;
    #pragma unroll
    for(int i=0;i<4;i++){ float d=v[i]-mean; sq += d*d; }
    red[t]=sq; __syncthreads();
    #pragma unroll
    for(int o=128;o>0;o>>=1){ if(t<o) red[t]+=red[t+o]; __syncthreads(); }
    float rstd = rsqrtf(red[0]*(1.f/Dm) + 1e-6f);
    float* orow = out + (size_t)row*Dm;
    #pragma unroll
    for(int i=0;i<4;i++){
        int c = t + 256*i;
        float y = (v[i]-mean)*rstd;
        if(sh_off >= 0) y = y*(1.f + mods[sc_off + c]) + mods[sh_off + c];
        orow[c] = y;
    }
}

// ---------------- 3D RoPE on q,k -------------------------------------------
__global__ void rope_qk(float* __restrict__ q, float* __restrict__ k,
                        const float* __restrict__ rope){
    int id = blockIdx.x*blockDim.x + threadIdx.x;
    if(id >= Lq*NH*32) return;
    int d = id & 31;
    int h = (id>>5) & (NH-1);
    int l = id >> 9;
    float a1 = rope[l*HDim + d], a2 = rope[l*HDim + d + 32];
    float s1,c1,s2,c2;
    sincosf(a1,&s1,&c1);
    sincosf(a2,&s2,&c2);
    size_t base = (size_t)l*Dm + h*HDim;
    float q1=q[base+d], q2=q[base+d+32];
    q[base+d]    = q1*c1 - q2*s1;
    q[base+d+32] = q2*c2 + q1*s2;
    float k1=k[base+d], k2=k[base+d+32];
    k[base+d]    = k1*c1 - k2*s1;
    k[base+d+32] = k2*c2 + k1*s2;
}

// ---------------- flash attention, fp32, HD=64 ------------------------------
// 128 threads: 2 threads per query row, each owns 32 of the 64 dims.
__global__ __launch_bounds__(128) void attn_fp32(
        const float* __restrict__ Q, const float* __restrict__ K,
        const float* __restrict__ V, float* __restrict__ O, int nkv){
    __shared__ float Ks[64][HDim];
    __shared__ float Vs[64][HDim];
    int h  = blockIdx.y;
    int q0 = blockIdx.x*64;
    int t  = threadIdx.x;
    int row = t>>1, half = t&1;
    float qv[32], acc[32];
    const float* qr = Q + (size_t)(q0+row)*Dm + h*HDim + half*32;
    #pragma unroll
    for(int d=0;d<32;d++){ qv[d]=qr[d]*0.125f; acc[d]=0.f; }
    float m = -1e30f, lsum = 0.f;
    for(int kv0=0; kv0<nkv; kv0+=64){
        #pragma unroll
        for(int i=0;i<8;i++){
            int idx = i*128 + t;
            int r = idx>>4, c = (idx&15)<<2;
            *(float4*)&Ks[r][c] = *(const float4*)(K + (size_t)(kv0+r)*Dm + h*HDim + c);
            *(float4*)&Vs[r][c] = *(const float4*)(V + (size_t)(kv0+r)*Dm + h*HDim + c);
        }
        __syncthreads();
        #pragma unroll 1
        for(int jc=0;jc<64;jc+=8){
            float s[8]; float tmax = -1e30f;
            #pragma unroll
            for(int j=0;j<8;j++){
                const float4* kr = (const float4*)&Ks[jc+j][half*32];
                float a0=0,a1=0,a2=0,a3=0;
                #pragma unroll
                for(int d4=0; d4<8; d4++){
                    float4 kk = kr[d4];
                    a0 += qv[d4*4+0]*kk.x; a1 += qv[d4*4+1]*kk.y;
                    a2 += qv[d4*4+2]*kk.z; a3 += qv[d4*4+3]*kk.w;
                }
                float part = (a0+a1)+(a2+a3);
                s[j] = part + __shfl_xor_sync(0xffffffffu, part, 1);
                tmax = fmaxf(tmax, s[j]);
            }
            float mnew = fmaxf(m, tmax);
            float corr = __expf(m - mnew);
            lsum *= corr;
            #pragma unroll
            for(int d=0;d<32;d++) acc[d]*=corr;
            #pragma unroll
            for(int j=0;j<8;j++){
                float p = __expf(s[j]-mnew);
                lsum += p;
                const float4* vr = (const float4*)&Vs[jc+j][half*32];
                #pragma unroll
                for(int d4=0;d4<8;d4++){
                    float4 vv = vr[d4];
                    acc[d4*4+0] += p*vv.x; acc[d4*4+1] += p*vv.y;
                    acc[d4*4+2] += p*vv.z; acc[d4*4+3] += p*vv.w;
                }
            }
            m = mnew;
        }
        __syncthreads();
    }
    float inv = 1.f/lsum;
    float* orow = O + (size_t)(q0+row)*Dm + h*HDim + half*32;
    #pragma unroll
    for(int d=0;d<32;d++) orow[d] = acc[d]*inv;
}

// ---------------- TF32 tensor-core GEMM NT: C[m,n] = sum_k A[m,k]*B[n,k] ----
// 128x128x16 tile, 256 threads (8 warps in 4x2), warp tile 32x64 via m16n8k8.
// gridDim.z selects among up to 3 (B,C) pairs sharing A.
// mode: 0 = (+bias), 1 = gelu(+bias), 2 = C += (+bias), 3 = C += gate[n]*(+bias)
#define SST 20   // smem row stride in floats (conflict-free for frag pattern)
__global__ __launch_bounds__(256) void tgemm(
        const float* __restrict__ A,
        const float* __restrict__ B0, const float* __restrict__ B1, const float* __restrict__ B2,
        float* __restrict__ C0, float* __restrict__ C1, float* __restrict__ C2,
        const float* __restrict__ bias, const float* __restrict__ gate,
        int M, int N, int K, int mode){
    const float* B = (blockIdx.z==0) ? B0 : (blockIdx.z==1 ? B1 : B2);
    float*       C = (blockIdx.z==0) ? C0 : (blockIdx.z==1 ? C1 : C2);

    __shared__ uint32_t As[128*SST];
    __shared__ uint32_t Bs[128*SST];

    int tid = threadIdx.x;
    int bm = blockIdx.y*128, bn = blockIdx.x*128;
    int lr = tid>>2, lc = (tid&3)*4;          // global-load coords
    const float* Ag  = A + (size_t)(bm+lr)*K + lc;
    const float* Ag2 = Ag + (size_t)64*K;
    const float* Bg  = B + (size_t)(bn+lr)*K + lc;
    const float* Bg2 = Bg + (size_t)64*K;

    int lane = tid&31, warp = tid>>5;
    int g = lane>>2, tig = lane&3;
    int wm0 = (warp>>1)*32, wn0 = (warp&1)*64;

    float acc[2][8][4];
    #pragma unroll
    for(int mi=0;mi<2;mi++)
        #pragma unroll
        for(int ni=0;ni<8;ni++)
            #pragma unroll
            for(int c=0;c<4;c++) acc[mi][ni][c]=0.f;

    float4 av0 = *(const float4*)Ag;
    float4 av1 = *(const float4*)Ag2;
    float4 bv0 = *(const float4*)Bg;
    float4 bv1 = *(const float4*)Bg2;

    int k0 = 0;
    for(;;){
        // store (with tf32 rounding) into smem
        *(uint4*)&As[lr*SST + lc]      = make_uint4(f2tf32(av0.x),f2tf32(av0.y),f2tf32(av0.z),f2tf32(av0.w));
        *(uint4*)&As[(lr+64)*SST + lc] = make_uint4(f2tf32(av1.x),f2tf32(av1.y),f2tf32(av1.z),f2tf32(av1.w));
        *(uint4*)&Bs[lr*SST + lc]      = make_uint4(f2tf32(bv0.x),f2tf32(bv0.y),f2tf32(bv0.z),f2tf32(bv0.w));
        *(uint4*)&Bs[(lr+64)*SST + lc] = make_uint4(f2tf32(bv1.x),f2tf32(bv1.y),f2tf32(bv1.z),f2tf32(bv1.w));
        __syncthreads();

        k0 += 16;
        bool more = (k0 < K);
        if(more){
            av0 = *(const float4*)(Ag + k0);
            av1 = *(const float4*)(Ag2 + k0);
            bv0 = *(const float4*)(Bg + k0);
            bv1 = *(const float4*)(Bg2 + k0);
        }

        #pragma unroll
        for(int ks=0; ks<16; ks+=8){
            uint32_t af[2][4], bf[8][2];
            #pragma unroll
            for(int mi=0;mi<2;mi++){
                int r = wm0 + mi*16 + g;
                af[mi][0] = As[r*SST     + ks + tig];
                af[mi][1] = As[(r+8)*SST + ks + tig];
                af[mi][2] = As[r*SST     + ks + tig + 4];
                af[mi][3] = As[(r+8)*SST + ks + tig + 4];
            }
            #pragma unroll
            for(int ni=0;ni<8;ni++){
                int rn = wn0 + ni*8 + g;
                bf[ni][0] = Bs[rn*SST + ks + tig];
                bf[ni][1] = Bs[rn*SST + ks + tig + 4];
            }
            #pragma unroll
            for(int mi=0;mi<2;mi++)
                #pragma unroll
                for(int ni=0;ni<8;ni++)
                    mma_tf32(acc[mi][ni], af[mi], bf[ni]);
        }
        __syncthreads();
        if(!more) break;
    }

    // epilogue
    #pragma unroll
    for(int mi=0;mi<2;mi++){
        int m0 = bm + wm0 + mi*16 + g;
        #pragma unroll
        for(int ni=0;ni<8;ni++){
            int n = bn + wn0 + ni*8 + 2*tig;
            float b0 = bias ? bias[n]   : 0.f;
            float b1 = bias ? bias[n+1] : 0.f;
            #pragma unroll
            for(int rr=0;rr<2;rr++){
                int m = m0 + rr*8;
                float v0 = acc[mi][ni][rr*2+0] + b0;
                float v1 = acc[mi][ni][rr*2+1] + b1;
                size_t off = (size_t)m*N + n;
                if(mode==1){
                    v0 = 0.5f*v0*(1.f + erff(v0*0.70710678118f));
                    v1 = 0.5f*v1*(1.f + erff(v1*0.70710678118f));
                } else if(mode==2){
                    v0 += C[off]; v1 += C[off+1];
                } else if(mode==3){
                    v0 = C[off]   + gate[n]  *v0;
                    v1 = C[off+1] + gate[n+1]*v1;
                }
                C[off] = v0; C[off+1] = v1;
            }
        }
    }
}

// ---------------- driver ----------------------------------------------------
extern "C" void kernel_launch(void* const* d_in, const int* in_sizes, int n_in,
                              void* d_out, int out_size){
    const float* x     = (const float*)d_in[0];
    const float* temb  = (const float*)d_in[1];
    const float* ctx   = (const float*)d_in[2];
    const float* rope  = (const float*)d_in[3];
    const float* adaW  = (const float*)d_in[4];
    const float* adab  = (const float*)d_in[5];
    const float* sqW   = (const float*)d_in[6];
    const float* skW   = (const float*)d_in[7];
    const float* svW   = (const float*)d_in[8];
    const float* soW   = (const float*)d_in[9];
    const float* sob   = (const float*)d_in[10];
    const float* cqW   = (const float*)d_in[11];
    const float* ckW   = (const float*)d_in[12];
    const float* cvW   = (const float*)d_in[13];
    const float* coW   = (const float*)d_in[14];
    const float* cob   = (const float*)d_in[15];
    const float* f1W   = (const float*)d_in[16];
    const float* f1b   = (const float*)d_in[17];
    const float* f2W   = (const float*)d_in[18];
    const float* f2b   = (const float*)d_in[19];

    float *px,*phx,*pff,*pq,*pk,*pv,*po,*pck,*pcv,*pmods;
    cudaGetSymbolAddress((void**)&px,   g_x);
    cudaGetSymbolAddress((void**)&phx,  g_hx);
    cudaGetSymbolAddress((void**)&pff,  g_ff);
    cudaGetSymbolAddress((void**)&pq,   g_q);
    cudaGetSymbolAddress((void**)&pk,   g_k);
    cudaGetSymbolAddress((void**)&pv,   g_v);
    cudaGetSymbolAddress((void**)&po,   g_o);
    cudaGetSymbolAddress((void**)&pck,  g_ck);
    cudaGetSymbolAddress((void**)&pcv,  g_cv);
    cudaGetSymbolAddress((void**)&pmods,g_mods);

    copy_kernel<<<(Lq*Dm/4+255)/256,256>>>(x, px, Lq*Dm/4);

    for(int i=0;i<NBlk;i++){
        const float* adaWi = adaW + (size_t)i*6*Dm*Dm;
        const float* adabi = adab + (size_t)i*6*Dm;
        const float* sqWi  = sqW  + (size_t)i*Dm*Dm;
        const float* skWi  = skW  + (size_t)i*Dm*Dm;
        const float* svWi  = svW  + (size_t)i*Dm*Dm;
        const float* soWi  = soW  + (size_t)i*Dm*Dm;
        const float* sobi  = sob  + (size_t)i*Dm;
        const float* cqWi  = cqW  + (size_t)i*Dm*Dm;
        const float* ckWi  = ckW  + (size_t)i*Dm*Dm;
        const float* cvWi  = cvW  + (size_t)i*Dm*Dm;
        const float* coWi  = coW  + (size_t)i*Dm*Dm;
        const float* cobi  = cob  + (size_t)i*Dm;
        const float* f1Wi  = f1W  + (size_t)i*DFFm*Dm;
        const float* f1bi  = f1b  + (size_t)i*DFFm;
        const float* f2Wi  = f2W  + (size_t)i*Dm*DFFm;
        const float* f2bi  = f2b  + (size_t)i*Dm;

        // adaLN modulation vector (6*D)
        mod_gemv<<<6*Dm/8,256>>>(temb, adaWi, adabi, pmods);

        // --- self attention ---
        ln_mod<<<Lq,256>>>(px, pmods, 0, Dm, phx);                       // shift_msa, scale_msa
        tgemm<<<dim3(Dm/128, Lq/128, 3),256>>>(phx, sqWi, skWi, svWi,
                                               pq, pk, pv, nullptr, nullptr,
                                               Lq, Dm, Dm, 0);
        rope_qk<<<(Lq*NH*32)/256,256>>>(pq, pk, rope);
        attn_fp32<<<dim3(Lq/64, NH),128>>>(pq, pk, pv, po, Lq);
        tgemm<<<dim3(Dm/128, Lq/128, 1),256>>>(po, soWi,nullptr,nullptr,
                                               px, nullptr,nullptr,
                                               sobi, pmods+2*Dm,        // gate_msa
                                               Lq, Dm, Dm, 3);

        // --- cross attention ---
        ln_mod<<<Lq,256>>>(px, pmods, -1, -1, phx);                      // plain LN
        tgemm<<<dim3(Dm/128, Lq/128, 1),256>>>(phx, cqWi,nullptr,nullptr,
                                               pq, nullptr,nullptr,
                                               nullptr, nullptr, Lq, Dm, Dm, 0);
        tgemm<<<dim3(Dm/128, Sc/128, 2),256>>>(ctx, ckWi, cvWi, nullptr,
                                               pck, pcv, nullptr,
                                               nullptr, nullptr, Sc, Dm, Dm, 0);
        attn_fp32<<<dim3(Lq/64, NH),128>>>(pq, pck, pcv, po, Sc);
        tgemm<<<dim3(Dm/128, Lq/128, 1),256>>>(po, coWi,nullptr,nullptr,
                                               px, nullptr,nullptr,
                                               cobi, nullptr, Lq, Dm, Dm, 2);

        // --- MLP ---
        ln_mod<<<Lq,256>>>(px, pmods, 3*Dm, 4*Dm, phx);                  // shift_mlp, scale_mlp
        tgemm<<<dim3(DFFm/128, Lq/128, 1),256>>>(phx, f1Wi,nullptr,nullptr,
                                                 pff, nullptr,nullptr,
                                                 f1bi, nullptr, Lq, DFFm, Dm, 1);
        tgemm<<<dim3(Dm/128, Lq/128, 1),256>>>(pff, f2Wi,nullptr,nullptr,
                                               px, nullptr,nullptr,
                                               f2bi, pmods+5*Dm,        // gate_mlp
                                               Lq, Dm, DFFm, 3);
    }

    copy_kernel<<<(Lq*Dm/4+255)/256,256>>>(px, (float*)d_out, Lq*Dm/4);
}